// round 1
// baseline (speedup 1.0000x reference)
#include <cuda_runtime.h>
#include <math.h>

// ---------------- problem constants ----------------
constexpr int BATCH = 64, HIMG = 56, WIMG = 56, CDIM = 192;
constexpr int HEADS = 6, HD = 32, WSZ = 7, SSZ = 3, NWG = 8, NTOK = 49;
constexpr int NWIN = BATCH * NWG * NWG;          // 4096
constexpr size_t ROWS = (size_t)NWIN * NTOK;     // 200704
constexpr int HID = 768, QKVC = 576;

// ---------------- scratch (device globals; no runtime alloc) ----------------
__device__ float g_xw [ROWS * CDIM];     // LN output (reused for LN1-windowed and LN2)
__device__ float g_qkv[ROWS * QKVC];     // qkv GEMM output
__device__ float g_att[ROWS * CDIM];     // attention output (window layout)
__device__ float g_hid[ROWS * HID];      // fc1/gelu output

// ---------------- LayerNorm (+ optional shift/window gather) ----------------
// one warp per row (C=192 = 32 lanes * 6)
template<bool WIN>
__global__ void __launch_bounds__(256) ln_kernel(const float* __restrict__ x,
                                                 const float* __restrict__ gg,
                                                 const float* __restrict__ bb)
{
    int warp = (blockIdx.x << 3) + (threadIdx.x >> 5);
    int lane = threadIdx.x & 31;
    size_t src;
    if (WIN) {
        int w = warp / NTOK, n = warp - w * NTOK;
        int bi = w >> 6, wi = w & 63, wh = wi >> 3, ww = wi & 7;
        int ii = n / WSZ, jj = n - ii * WSZ;
        int hs = wh * WSZ + ii + SSZ; if (hs >= HIMG) hs -= HIMG;   // roll(-ss)
        int ws_ = ww * WSZ + jj + SSZ; if (ws_ >= WIMG) ws_ -= WIMG;
        src = ((size_t)bi * (HIMG * WIMG) + (size_t)hs * WIMG + ws_) * CDIM;
    } else {
        src = (size_t)warp * CDIM;
    }
    const float* xr = x + src;
    float v[6]; float s = 0.f;
#pragma unroll
    for (int t = 0; t < 6; t++) { v[t] = xr[lane + 32 * t]; s += v[t]; }
#pragma unroll
    for (int o = 16; o; o >>= 1) s += __shfl_xor_sync(0xffffffffu, s, o);
    float mu = s * (1.0f / CDIM);
    float vs = 0.f;
#pragma unroll
    for (int t = 0; t < 6; t++) { float d = v[t] - mu; vs += d * d; }
#pragma unroll
    for (int o = 16; o; o >>= 1) vs += __shfl_xor_sync(0xffffffffu, vs, o);
    float inv = rsqrtf(vs * (1.0f / CDIM) + 1e-5f);
    float* op = g_xw + (size_t)warp * CDIM;
#pragma unroll
    for (int t = 0; t < 6; t++) {
        int c = lane + 32 * t;
        op[c] = (v[t] - mu) * inv * gg[c] + bb[c];
    }
}

// ---------------- SGEMM: C[m][n] = sum_k A[m][k] * W[n][k]  (+ epilogue) ----
// BM=128, BN=64, BK=16, 256 threads, 8x4 per thread.
enum { EPI_QKV = 0, EPI_PROJ = 1, EPI_FC1 = 2, EPI_FC2 = 3 };

__device__ __forceinline__ float gelu_exact(float v) {
    return 0.5f * v * (1.0f + erff(v * 0.70710678118654752f));
}

template<int KD, int EPI>
__global__ void __launch_bounds__(256) gemm_kernel(
    const float* __restrict__ A, const float* __restrict__ Wm,
    const float* __restrict__ bias, float* __restrict__ outp,
    const float* __restrict__ extra)
{
    __shared__ float As[16][128];
    __shared__ float Bs[16][64];
    const int t  = threadIdx.x;
    const int m0 = blockIdx.y * 128, n0 = blockIdx.x * 64;
    const int ty = t >> 4, tx = t & 15;
    const int arow = t >> 1, akq = (t & 1) * 8;
    const int brow = t >> 2, bkq = (t & 3) * 4;
    const float* Ap = A  + (size_t)(m0 + arow) * KD + akq;
    const float* Bp = Wm + (size_t)(n0 + brow) * KD + bkq;

    float acc[8][4];
#pragma unroll
    for (int i = 0; i < 8; i++)
#pragma unroll
        for (int j = 0; j < 4; j++) acc[i][j] = 0.f;

    for (int k0 = 0; k0 < KD; k0 += 16) {
        float4 a0 = *(const float4*)(Ap + k0);
        float4 a1 = *(const float4*)(Ap + k0 + 4);
        float4 b0 = *(const float4*)(Bp + k0);
        As[akq + 0][arow] = a0.x; As[akq + 1][arow] = a0.y;
        As[akq + 2][arow] = a0.z; As[akq + 3][arow] = a0.w;
        As[akq + 4][arow] = a1.x; As[akq + 5][arow] = a1.y;
        As[akq + 6][arow] = a1.z; As[akq + 7][arow] = a1.w;
        Bs[bkq + 0][brow] = b0.x; Bs[bkq + 1][brow] = b0.y;
        Bs[bkq + 2][brow] = b0.z; Bs[bkq + 3][brow] = b0.w;
        __syncthreads();
#pragma unroll
        for (int kk = 0; kk < 16; kk++) {
            float4 av0 = *(const float4*)&As[kk][ty * 8];
            float4 av1 = *(const float4*)&As[kk][ty * 8 + 4];
            float4 bv  = *(const float4*)&Bs[kk][tx * 4];
            float ar[8] = {av0.x, av0.y, av0.z, av0.w, av1.x, av1.y, av1.z, av1.w};
            float br[4] = {bv.x, bv.y, bv.z, bv.w};
#pragma unroll
            for (int i = 0; i < 8; i++)
#pragma unroll
                for (int j = 0; j < 4; j++) acc[i][j] += ar[i] * br[j];
        }
        __syncthreads();
    }

    const int cb = n0 + tx * 4;
    float4 bsv = *(const float4*)(bias + cb);
#pragma unroll
    for (int i = 0; i < 8; i++) {
        int r = m0 + ty * 8 + i;
        float4 v;
        v.x = acc[i][0] + bsv.x; v.y = acc[i][1] + bsv.y;
        v.z = acc[i][2] + bsv.z; v.w = acc[i][3] + bsv.w;
        if (EPI == EPI_QKV) {
            *(float4*)(outp + (size_t)r * QKVC + cb) = v;
        } else if (EPI == EPI_PROJ) {
            // window-reverse + roll(+ss) + residual-add, scatter into d_out
            int w = r / NTOK, n = r - w * NTOK;
            int bi = w >> 6, wi = w & 63, wh = wi >> 3, ww = wi & 7;
            int ii = n / WSZ, jj = n - ii * WSZ;
            int hp = wh * WSZ + ii + SSZ; if (hp >= HIMG) hp -= HIMG;
            int wp = ww * WSZ + jj + SSZ; if (wp >= WIMG) wp -= WIMG;
            size_t dst = ((size_t)bi * (HIMG * WIMG) + (size_t)hp * WIMG + wp) * CDIM + cb;
            float4 xv = *(const float4*)(extra + dst);
            v.x += xv.x; v.y += xv.y; v.z += xv.z; v.w += xv.w;
            *(float4*)(outp + dst) = v;
        } else if (EPI == EPI_FC1) {
            v.x = gelu_exact(v.x); v.y = gelu_exact(v.y);
            v.z = gelu_exact(v.z); v.w = gelu_exact(v.w);
            *(float4*)(outp + (size_t)r * HID + cb) = v;
        } else { // EPI_FC2: += residual (in-place on d_out)
            float4 xv = *(const float4*)(outp + (size_t)r * CDIM + cb);
            v.x += xv.x; v.y += xv.y; v.z += xv.z; v.w += xv.w;
            *(float4*)(outp + (size_t)r * CDIM + cb) = v;
        }
    }
}

// ---------------- window attention: one block per (window, head) -----------
__global__ void __launch_bounds__(256) attn_kernel(const float* __restrict__ bias_table)
{
    __shared__ float qs[NTOK][HD + 1], ks[NTOK][HD + 1], vs[NTOK][HD + 1];
    __shared__ float sc[NTOK][NTOK + 1];
    __shared__ float biasS[169];
    __shared__ int   regid[NTOK];

    const int blk = blockIdx.x;
    const int w = blk / HEADS, h = blk - w * HEADS;
    const int t = threadIdx.x;

    const float* qbase = g_qkv + (size_t)w * NTOK * QKVC + h * HD;
    for (int e = t; e < NTOK * HD; e += 256) {
        int n = e >> 5, d = e & 31;
        const float* row = qbase + (size_t)n * QKVC + d;
        qs[n][d] = row[0];
        ks[n][d] = row[CDIM];
        vs[n][d] = row[2 * CDIM];
    }
    for (int e = t; e < 169; e += 256) biasS[e] = bias_table[e * HEADS + h];
    if (t < NTOK) {
        int wi = w & 63, wh = wi >> 3, ww = wi & 7;
        int ii = t / WSZ, jj = t - ii * WSZ;
        int p = wh * WSZ + ii, q = ww * WSZ + jj;
        int rh = p < (HIMG - WSZ) ? 0 : (p < (HIMG - SSZ) ? 1 : 2);
        int rw = q < (WIMG - WSZ) ? 0 : (q < (WIMG - SSZ) ? 1 : 2);
        regid[t] = rh * 3 + rw;
    }
    __syncthreads();

    const float scale = 0.17677669529663688f; // 32^-0.5
    for (int e = t; e < NTOK * NTOK; e += 256) {
        int n = e / NTOK, m = e - n * NTOK;
        float a = 0.f;
#pragma unroll
        for (int d = 0; d < HD; d++) a += qs[n][d] * ks[m][d];
        int i1 = n / WSZ, j1 = n - i1 * WSZ;
        int i2 = m / WSZ, j2 = m - i2 * WSZ;
        int idx = (i1 - i2 + WSZ - 1) * (2 * WSZ - 1) + (j1 - j2 + WSZ - 1);
        float msk = (regid[n] == regid[m]) ? 0.f : -100.f;
        sc[n][m] = a * scale + biasS[idx] + msk;
    }
    __syncthreads();

    if (t < NTOK) {
        float mx = -1e30f;
        for (int m = 0; m < NTOK; m++) mx = fmaxf(mx, sc[t][m]);
        float s = 0.f;
        for (int m = 0; m < NTOK; m++) { float e = expf(sc[t][m] - mx); sc[t][m] = e; s += e; }
        float inv = 1.0f / s;
        for (int m = 0; m < NTOK; m++) sc[t][m] *= inv;
    }
    __syncthreads();

    float* obase = g_att + (size_t)w * NTOK * CDIM + h * HD;
    for (int e = t; e < NTOK * HD; e += 256) {
        int n = e >> 5, d = e & 31;
        float a = 0.f;
#pragma unroll
        for (int m = 0; m < NTOK; m++) a += sc[n][m] * vs[m][d];
        obase[(size_t)n * CDIM + d] = a;
    }
}

// ---------------- launch ----------------------------------------------------
extern "C" void kernel_launch(void* const* d_in, const int* in_sizes, int n_in,
                              void* d_out, int out_size)
{
    const float* x      = (const float*)d_in[0];
    const float* n1g    = (const float*)d_in[1];
    const float* n1b    = (const float*)d_in[2];
    const float* qkv_w  = (const float*)d_in[3];
    const float* qkv_b  = (const float*)d_in[4];
    const float* relb   = (const float*)d_in[5];
    const float* proj_w = (const float*)d_in[6];
    const float* proj_b = (const float*)d_in[7];
    const float* n2g    = (const float*)d_in[8];
    const float* n2b    = (const float*)d_in[9];
    const float* fc1_w  = (const float*)d_in[10];
    const float* fc1_b  = (const float*)d_in[11];
    const float* fc2_w  = (const float*)d_in[12];
    const float* fc2_b  = (const float*)d_in[13];
    float* out = (float*)d_out;

    float *pxw, *pqkv, *patt, *phid;
    cudaGetSymbolAddress((void**)&pxw,  g_xw);
    cudaGetSymbolAddress((void**)&pqkv, g_qkv);
    cudaGetSymbolAddress((void**)&patt, g_att);
    cudaGetSymbolAddress((void**)&phid, g_hid);

    const int LN_BLOCKS = (int)(ROWS / 8);       // 25088 (8 warps/block)
    const int MB = (int)(ROWS / 128);            // 1568

    // 1) LN1 + shift + window partition
    ln_kernel<true><<<LN_BLOCKS, 256>>>(x, n1g, n1b);
    // 2) QKV GEMM (200704 x 192 x 576)
    gemm_kernel<192, EPI_QKV><<<dim3(QKVC / 64, MB), 256>>>(pxw, qkv_w, qkv_b, pqkv, nullptr);
    // 3) window attention
    attn_kernel<<<NWIN * HEADS, 256>>>(relb);
    // 4) proj GEMM + window-reverse + roll-back + residual (writes full d_out)
    gemm_kernel<192, EPI_PROJ><<<dim3(CDIM / 64, MB), 256>>>(patt, proj_w, proj_b, out, x);
    // 5) LN2
    ln_kernel<false><<<LN_BLOCKS, 256>>>(out, n2g, n2b);
    // 6) fc1 + GELU
    gemm_kernel<192, EPI_FC1><<<dim3(HID / 64, MB), 256>>>(pxw, fc1_w, fc1_b, phid, nullptr);
    // 7) fc2 + residual
    gemm_kernel<768, EPI_FC2><<<dim3(CDIM / 64, MB), 256>>>(phid, fc2_w, fc2_b, out, nullptr);
}

// round 2
// speedup vs baseline: 1.6036x; 1.6036x over previous
#include <cuda_runtime.h>
#include <math.h>
#include <stdint.h>

// ---------------- problem constants ----------------
constexpr int BATCH = 64, HIMG = 56, WIMG = 56, CDIM = 192;
constexpr int HEADS = 6, HD = 32, WSZ = 7, SSZ = 3, NWG = 8, NTOK = 49;
constexpr int NWIN = BATCH * NWG * NWG;          // 4096
constexpr size_t ROWS = (size_t)NWIN * NTOK;     // 200704
constexpr int HID = 768, QKVC = 576;

// ---------------- scratch (device globals; no runtime alloc) ----------------
__device__ float g_xw [ROWS * CDIM];
__device__ float g_qkv[ROWS * QKVC];
__device__ float g_att[ROWS * CDIM];
__device__ float g_hid[ROWS * HID];

// ---------------- LayerNorm (+ optional shift/window gather) ----------------
template<bool WIN>
__global__ void __launch_bounds__(256) ln_kernel(const float* __restrict__ x,
                                                 const float* __restrict__ gg,
                                                 const float* __restrict__ bb)
{
    int warp = (blockIdx.x << 3) + (threadIdx.x >> 5);
    int lane = threadIdx.x & 31;
    size_t src;
    if (WIN) {
        int w = warp / NTOK, n = warp - w * NTOK;
        int bi = w >> 6, wi = w & 63, wh = wi >> 3, ww = wi & 7;
        int ii = n / WSZ, jj = n - ii * WSZ;
        int hs = wh * WSZ + ii + SSZ; if (hs >= HIMG) hs -= HIMG;
        int ws_ = ww * WSZ + jj + SSZ; if (ws_ >= WIMG) ws_ -= WIMG;
        src = ((size_t)bi * (HIMG * WIMG) + (size_t)hs * WIMG + ws_) * CDIM;
    } else {
        src = (size_t)warp * CDIM;
    }
    const float* xr = x + src;
    float v[6]; float s = 0.f;
#pragma unroll
    for (int t = 0; t < 6; t++) { v[t] = xr[lane + 32 * t]; s += v[t]; }
#pragma unroll
    for (int o = 16; o; o >>= 1) s += __shfl_xor_sync(0xffffffffu, s, o);
    float mu = s * (1.0f / CDIM);
    float vs = 0.f;
#pragma unroll
    for (int t = 0; t < 6; t++) { float d = v[t] - mu; vs += d * d; }
#pragma unroll
    for (int o = 16; o; o >>= 1) vs += __shfl_xor_sync(0xffffffffu, vs, o);
    float inv = rsqrtf(vs * (1.0f / CDIM) + 1e-5f);
    float* op = g_xw + (size_t)warp * CDIM;
#pragma unroll
    for (int t = 0; t < 6; t++) {
        int c = lane + 32 * t;
        op[c] = (v[t] - mu) * inv * gg[c] + bb[c];
    }
}

// ---------------- TF32 tensor-core GEMM --------------------------------------
// C[m][n] = sum_k A[m][k] * W[n][k]  via mma.sync.m16n8k8.tf32
// BM=256, BN=64, BK=16; 8 warps (4M x 2N), warp tile 64x32.
enum { EPI_QKV = 0, EPI_PROJ = 1, EPI_FC1 = 2, EPI_FC2 = 3 };

__device__ __forceinline__ float gelu_exact(float v) {
    return 0.5f * v * (1.0f + erff(v * 0.70710678118654752f));
}
__device__ __forceinline__ uint32_t f2tf32(float f) {
    uint32_t r;
    asm("cvt.rna.tf32.f32 %0, %1;" : "=r"(r) : "f"(f));
    return r;
}
__device__ __forceinline__ void mma_tf32(float* c, const uint32_t* a, const uint32_t* b) {
    asm volatile(
        "mma.sync.aligned.m16n8k8.row.col.f32.tf32.tf32.f32 "
        "{%0,%1,%2,%3}, {%4,%5,%6,%7}, {%8,%9}, {%0,%1,%2,%3};"
        : "+f"(c[0]), "+f"(c[1]), "+f"(c[2]), "+f"(c[3])
        : "r"(a[0]), "r"(a[1]), "r"(a[2]), "r"(a[3]), "r"(b[0]), "r"(b[1]));
}

template<int KD, int EPI>
__global__ void __launch_bounds__(256) gemm_tc(
    const float* __restrict__ A, const float* __restrict__ Wm,
    const float* __restrict__ bias, float* __restrict__ outp,
    const float* __restrict__ extra)
{
    constexpr int BM = 256, BN = 64, BK = 16;
    constexpr int ASTR = BM + 8;   // stride % 32 == 8 -> conflict-free frag loads
    constexpr int BSTR = BN + 8;
    __shared__ uint32_t As[BK][ASTR];
    __shared__ uint32_t Bs[BK][BSTR];

    const int t = threadIdx.x, lane = t & 31, wid = t >> 5;
    const int warpM = wid & 3, warpN = wid >> 2;     // 4 x 2
    const int m0 = blockIdx.y * BM, n0 = blockIdx.x * BN;
    const int gid = lane >> 2, tig = lane & 3;

    float acc[4][4][4];
#pragma unroll
    for (int i = 0; i < 4; i++)
#pragma unroll
        for (int j = 0; j < 4; j++)
#pragma unroll
            for (int r = 0; r < 4; r++) acc[i][j][r] = 0.f;

    const int lr = t >> 2;            // 0..63
    const int lc = (t & 3) * 4;       // 0,4,8,12

    for (int k0 = 0; k0 < KD; k0 += BK) {
        // global loads (coalesced 64B/warp segments)
        float4 av[4];
#pragma unroll
        for (int p = 0; p < 4; p++)
            av[p] = *(const float4*)(A + (size_t)(m0 + p * 64 + lr) * KD + k0 + lc);
        float4 bv = *(const float4*)(Wm + (size_t)(n0 + lr) * KD + k0 + lc);

        __syncthreads();
        // swizzled fill (avoids 4-way store conflicts)
#pragma unroll
        for (int p = 0; p < 4; p++) {
            float va[4] = {av[p].x, av[p].y, av[p].z, av[p].w};
#pragma unroll
            for (int j = 0; j < 4; j++) {
                int jj = (j + (t & 3)) & 3;
                As[lc + jj][p * 64 + lr] = f2tf32(va[jj]);
            }
        }
        {
            float vb[4] = {bv.x, bv.y, bv.z, bv.w};
#pragma unroll
            for (int j = 0; j < 4; j++) {
                int jj = (j + (t & 3)) & 3;
                Bs[lc + jj][lr] = f2tf32(vb[jj]);
            }
        }
        __syncthreads();

#pragma unroll
        for (int ks = 0; ks < BK; ks += 8) {
            uint32_t af[4][4], bf[4][2];
#pragma unroll
            for (int mt = 0; mt < 4; mt++) {
                int mr = warpM * 64 + mt * 16 + gid;
                af[mt][0] = As[ks + tig][mr];
                af[mt][1] = As[ks + tig][mr + 8];
                af[mt][2] = As[ks + tig + 4][mr];
                af[mt][3] = As[ks + tig + 4][mr + 8];
            }
#pragma unroll
            for (int nt = 0; nt < 4; nt++) {
                int nc = warpN * 32 + nt * 8 + gid;
                bf[nt][0] = Bs[ks + tig][nc];
                bf[nt][1] = Bs[ks + tig + 4][nc];
            }
#pragma unroll
            for (int mt = 0; mt < 4; mt++)
#pragma unroll
                for (int nt = 0; nt < 4; nt++)
                    mma_tf32(acc[mt][nt], af[mt], bf[nt]);
        }
    }

    // ----- epilogue -----
    const int mbase = m0 + warpM * 64;
    const int nbase = n0 + warpN * 32;
#pragma unroll
    for (int mt = 0; mt < 4; mt++) {
#pragma unroll
        for (int h = 0; h < 2; h++) {
            int r = mbase + mt * 16 + gid + h * 8;
            size_t dstrow = 0;
            if (EPI == EPI_PROJ) {
                int w = r / NTOK, n = r - w * NTOK;
                int bi = w >> 6, wi = w & 63, wh = wi >> 3, ww = wi & 7;
                int ii = n / WSZ, jj = n - ii * WSZ;
                int hp = wh * WSZ + ii + SSZ; if (hp >= HIMG) hp -= HIMG;
                int wp = ww * WSZ + jj + SSZ; if (wp >= WIMG) wp -= WIMG;
                dstrow = ((size_t)bi * (HIMG * WIMG) + (size_t)hp * WIMG + wp);
            }
#pragma unroll
            for (int nt = 0; nt < 4; nt++) {
                int n = nbase + nt * 8 + tig * 2;
                float2 bsv = *(const float2*)(bias + n);
                float2 v;
                v.x = acc[mt][nt][2 * h]     + bsv.x;
                v.y = acc[mt][nt][2 * h + 1] + bsv.y;
                if (EPI == EPI_QKV) {
                    *(float2*)(outp + (size_t)r * QKVC + n) = v;
                } else if (EPI == EPI_PROJ) {
                    size_t dst = dstrow * CDIM + n;
                    float2 xv = *(const float2*)(extra + dst);
                    v.x += xv.x; v.y += xv.y;
                    *(float2*)(outp + dst) = v;
                } else if (EPI == EPI_FC1) {
                    v.x = gelu_exact(v.x); v.y = gelu_exact(v.y);
                    *(float2*)(outp + (size_t)r * HID + n) = v;
                } else { // EPI_FC2
                    float2 xv = *(const float2*)(outp + (size_t)r * CDIM + n);
                    v.x += xv.x; v.y += xv.y;
                    *(float2*)(outp + (size_t)r * CDIM + n) = v;
                }
            }
        }
    }
}

// ---------------- window attention: one block per (window, head) -----------
__global__ void __launch_bounds__(256) attn_kernel(const float* __restrict__ bias_table)
{
    __shared__ float qs[NTOK][HD + 1], ks[NTOK][HD + 1], vs[NTOK][HD + 1];
    __shared__ float sc[NTOK][NTOK + 1];
    __shared__ float biasS[169];
    __shared__ int   regid[NTOK];

    const int blk = blockIdx.x;
    const int w = blk / HEADS, h = blk - w * HEADS;
    const int t = threadIdx.x;

    const float* qbase = g_qkv + (size_t)w * NTOK * QKVC + h * HD;
    for (int e = t; e < NTOK * HD; e += 256) {
        int n = e >> 5, d = e & 31;
        const float* row = qbase + (size_t)n * QKVC + d;
        qs[n][d] = row[0];
        ks[n][d] = row[CDIM];
        vs[n][d] = row[2 * CDIM];
    }
    for (int e = t; e < 169; e += 256) biasS[e] = bias_table[e * HEADS + h];
    if (t < NTOK) {
        int wi = w & 63, wh = wi >> 3, ww = wi & 7;
        int ii = t / WSZ, jj = t - ii * WSZ;
        int p = wh * WSZ + ii, q = ww * WSZ + jj;
        int rh = p < (HIMG - WSZ) ? 0 : (p < (HIMG - SSZ) ? 1 : 2);
        int rw = q < (WIMG - WSZ) ? 0 : (q < (WIMG - SSZ) ? 1 : 2);
        regid[t] = rh * 3 + rw;
    }
    __syncthreads();

    const float scale = 0.17677669529663688f;
    for (int e = t; e < NTOK * NTOK; e += 256) {
        int n = e / NTOK, m = e - n * NTOK;
        float a = 0.f;
#pragma unroll
        for (int d = 0; d < HD; d++) a += qs[n][d] * ks[m][d];
        int i1 = n / WSZ, j1 = n - i1 * WSZ;
        int i2 = m / WSZ, j2 = m - i2 * WSZ;
        int idx = (i1 - i2 + WSZ - 1) * (2 * WSZ - 1) + (j1 - j2 + WSZ - 1);
        float msk = (regid[n] == regid[m]) ? 0.f : -100.f;
        sc[n][m] = a * scale + biasS[idx] + msk;
    }
    __syncthreads();

    if (t < NTOK) {
        float mx = -1e30f;
        for (int m = 0; m < NTOK; m++) mx = fmaxf(mx, sc[t][m]);
        float s = 0.f;
        for (int m = 0; m < NTOK; m++) { float e = expf(sc[t][m] - mx); sc[t][m] = e; s += e; }
        float inv = 1.0f / s;
        for (int m = 0; m < NTOK; m++) sc[t][m] *= inv;
    }
    __syncthreads();

    float* obase = g_att + (size_t)w * NTOK * CDIM + h * HD;
    for (int e = t; e < NTOK * HD; e += 256) {
        int n = e >> 5, d = e & 31;
        float a = 0.f;
#pragma unroll
        for (int m = 0; m < NTOK; m++) a += sc[n][m] * vs[m][d];
        obase[(size_t)n * CDIM + d] = a;
    }
}

// ---------------- launch ----------------------------------------------------
extern "C" void kernel_launch(void* const* d_in, const int* in_sizes, int n_in,
                              void* d_out, int out_size)
{
    const float* x      = (const float*)d_in[0];
    const float* n1g    = (const float*)d_in[1];
    const float* n1b    = (const float*)d_in[2];
    const float* qkv_w  = (const float*)d_in[3];
    const float* qkv_b  = (const float*)d_in[4];
    const float* relb   = (const float*)d_in[5];
    const float* proj_w = (const float*)d_in[6];
    const float* proj_b = (const float*)d_in[7];
    const float* n2g    = (const float*)d_in[8];
    const float* n2b    = (const float*)d_in[9];
    const float* fc1_w  = (const float*)d_in[10];
    const float* fc1_b  = (const float*)d_in[11];
    const float* fc2_w  = (const float*)d_in[12];
    const float* fc2_b  = (const float*)d_in[13];
    float* out = (float*)d_out;

    float *pxw, *pqkv, *patt, *phid;
    cudaGetSymbolAddress((void**)&pxw,  g_xw);
    cudaGetSymbolAddress((void**)&pqkv, g_qkv);
    cudaGetSymbolAddress((void**)&patt, g_att);
    cudaGetSymbolAddress((void**)&phid, g_hid);

    const int LN_BLOCKS = (int)(ROWS / 8);       // 25088
    const int MB = (int)(ROWS / 256);            // 784

    // 1) LN1 + shift + window partition
    ln_kernel<true><<<LN_BLOCKS, 256>>>(x, n1g, n1b);
    // 2) QKV GEMM (200704 x 576 x 192)
    gemm_tc<192, EPI_QKV><<<dim3(QKVC / 64, MB), 256>>>(pxw, qkv_w, qkv_b, pqkv, nullptr);
    // 3) window attention
    attn_kernel<<<NWIN * HEADS, 256>>>(relb);
    // 4) proj GEMM + window-reverse + roll-back + residual
    gemm_tc<192, EPI_PROJ><<<dim3(CDIM / 64, MB), 256>>>(patt, proj_w, proj_b, out, x);
    // 5) LN2
    ln_kernel<false><<<LN_BLOCKS, 256>>>(out, n2g, n2b);
    // 6) fc1 + GELU
    gemm_tc<192, EPI_FC1><<<dim3(HID / 64, MB), 256>>>(pxw, fc1_w, fc1_b, phid, nullptr);
    // 7) fc2 + residual
    gemm_tc<768, EPI_FC2><<<dim3(CDIM / 64, MB), 256>>>(phid, fc2_w, fc2_b, out, nullptr);
}

// round 3
// speedup vs baseline: 2.3409x; 1.4598x over previous
#include <cuda_runtime.h>
#include <cuda_bf16.h>
#include <math.h>
#include <stdint.h>

// ---------------- problem constants ----------------
constexpr int BATCH = 64, HIMG = 56, WIMG = 56, CDIM = 192;
constexpr int HEADS = 6, HD = 32, WSZ = 7, SSZ = 3, NWG = 8, NTOK = 49;
constexpr int NWIN = BATCH * NWG * NWG;          // 4096
constexpr size_t ROWS = (size_t)NWIN * NTOK;     // 200704
constexpr int HID = 768, QKVC = 576;

// ---------------- scratch (device globals; no runtime alloc) ----------------
__device__ __nv_bfloat16 g_xw [ROWS * CDIM];
__device__ __nv_bfloat16 g_qkv[ROWS * QKVC];
__device__ __nv_bfloat16 g_att[ROWS * CDIM];
__device__ __nv_bfloat16 g_hid[ROWS * HID];
__device__ __nv_bfloat16 g_wqkv[QKVC * CDIM];
__device__ __nv_bfloat16 g_wproj[CDIM * CDIM];
__device__ __nv_bfloat16 g_wfc1[HID * CDIM];
__device__ __nv_bfloat16 g_wfc2[CDIM * HID];

// ---------------- weight conversion ----------------
__global__ void w2bf_kernel(const float* __restrict__ s, __nv_bfloat16* __restrict__ d, int n)
{
    int i = blockIdx.x * blockDim.x + threadIdx.x;
    if (i < n) d[i] = __float2bfloat16(s[i]);
}

// ---------------- LayerNorm (+ optional shift/window gather), bf16 out ------
template<bool WIN>
__global__ void __launch_bounds__(256) ln_kernel(const float* __restrict__ x,
                                                 const float* __restrict__ gg,
                                                 const float* __restrict__ bb)
{
    int warp = (blockIdx.x << 3) + (threadIdx.x >> 5);
    int lane = threadIdx.x & 31;
    size_t src;
    if (WIN) {
        int w = warp / NTOK, n = warp - w * NTOK;
        int bi = w >> 6, wi = w & 63, wh = wi >> 3, ww = wi & 7;
        int ii = n / WSZ, jj = n - ii * WSZ;
        int hs = wh * WSZ + ii + SSZ; if (hs >= HIMG) hs -= HIMG;
        int ws_ = ww * WSZ + jj + SSZ; if (ws_ >= WIMG) ws_ -= WIMG;
        src = ((size_t)bi * (HIMG * WIMG) + (size_t)hs * WIMG + ws_) * CDIM;
    } else {
        src = (size_t)warp * CDIM;
    }
    const float* xr = x + src;
    float v[6]; float s = 0.f;
#pragma unroll
    for (int t = 0; t < 6; t++) { v[t] = xr[lane + 32 * t]; s += v[t]; }
#pragma unroll
    for (int o = 16; o; o >>= 1) s += __shfl_xor_sync(0xffffffffu, s, o);
    float mu = s * (1.0f / CDIM);
    float vs = 0.f;
#pragma unroll
    for (int t = 0; t < 6; t++) { float d = v[t] - mu; vs += d * d; }
#pragma unroll
    for (int o = 16; o; o >>= 1) vs += __shfl_xor_sync(0xffffffffu, vs, o);
    float inv = rsqrtf(vs * (1.0f / CDIM) + 1e-5f);
    __nv_bfloat16* op = g_xw + (size_t)warp * CDIM;
#pragma unroll
    for (int t = 0; t < 6; t++) {
        int c = lane + 32 * t;
        op[c] = __float2bfloat16((v[t] - mu) * inv * gg[c] + bb[c]);
    }
}

// ---------------- bf16 tensor-core GEMM --------------------------------------
// C[m][n] = sum_k A[m][k] * W[n][k], mma.m16n8k16.bf16, ldmatrix, double buffer
// BM=128, BN=64, BK=32; 8 warps as 4(M) x 2(N), warp tile 32x32.
enum { EPI_QKV = 0, EPI_PROJ = 1, EPI_FC1 = 2, EPI_FC2 = 3 };

__device__ __forceinline__ float gelu_exact(float v) {
    return 0.5f * v * (1.0f + erff(v * 0.70710678118654752f));
}
__device__ __forceinline__ void ldsm4(uint32_t* r, uint32_t addr) {
    asm volatile("ldmatrix.sync.aligned.m8n8.x4.shared.b16 {%0,%1,%2,%3}, [%4];"
        : "=r"(r[0]), "=r"(r[1]), "=r"(r[2]), "=r"(r[3]) : "r"(addr));
}
__device__ __forceinline__ void mma_bf(float* c, const uint32_t* a, uint32_t b0, uint32_t b1) {
    asm volatile(
        "mma.sync.aligned.m16n8k16.row.col.f32.bf16.bf16.f32 "
        "{%0,%1,%2,%3}, {%4,%5,%6,%7}, {%8,%9}, {%0,%1,%2,%3};"
        : "+f"(c[0]), "+f"(c[1]), "+f"(c[2]), "+f"(c[3])
        : "r"(a[0]), "r"(a[1]), "r"(a[2]), "r"(a[3]), "r"(b0), "r"(b1));
}

template<int KD, int EPI>
__global__ void __launch_bounds__(256) gemm_bf(
    const __nv_bfloat16* __restrict__ A, const __nv_bfloat16* __restrict__ Wm,
    const float* __restrict__ bias, float* __restrict__ outf,
    __nv_bfloat16* __restrict__ outb, const float* __restrict__ extra)
{
    // SMEM: As[2][128 rows][40 bf16 (=20 u32)], Bs[2][64][40 bf16]
    __shared__ uint32_t sm[2 * 2560 + 2 * 1280];
    const int t = threadIdx.x, lane = t & 31, wid = t >> 5;
    const int warpM = wid & 3, warpN = wid >> 2;      // 4 x 2
    const int m0 = blockIdx.y * 128, n0 = blockIdx.x * 64;
    const int gid = lane >> 2, tig = lane & 3;

    const int lr = t >> 2, seg = t & 3;               // gmem load assignment
    const __nv_bfloat16* Ap0 = A + (size_t)(m0 + lr) * KD + seg * 8;
    const __nv_bfloat16* Ap1 = A + (size_t)(m0 + 64 + lr) * KD + seg * 8;
    const __nv_bfloat16* Bp  = Wm + (size_t)(n0 + lr) * KD + seg * 8;

    // ldmatrix shared addresses (bytes), row stride = 80B
    uint32_t smbase = (uint32_t)__cvta_generic_to_shared(sm);
    uint32_t aAddr0 = smbase + (uint32_t)((warpM * 32 + (lane & 15)) * 80 + (lane >> 4) * 16);
    uint32_t aAddr1 = aAddr0 + 16 * 80;
    uint32_t bRow   = (uint32_t)(warpN * 32 + (lane & 7) + ((lane & 16) >> 1));
    uint32_t bAddr0 = smbase + 20480u + bRow * 80 + ((lane >> 3) & 1) * 16;
    uint32_t bAddr1 = bAddr0 + 16 * 80;

    float acc[2][4][4];
#pragma unroll
    for (int i = 0; i < 2; i++)
#pragma unroll
        for (int j = 0; j < 4; j++)
#pragma unroll
            for (int r = 0; r < 4; r++) acc[i][j][r] = 0.f;

    const int sbase = lr * 20 + seg * 4;
    auto store_tile = [&](int buf, const uint4& a0, const uint4& a1, const uint4& b) {
        const uint32_t* p0 = (const uint32_t*)&a0;
        const uint32_t* p1 = (const uint32_t*)&a1;
        const uint32_t* pb = (const uint32_t*)&b;
        uint32_t* Ad = sm + buf * 2560 + sbase;
        uint32_t* Bd = sm + 5120 + buf * 1280 + sbase;
#pragma unroll
        for (int i = 0; i < 4; i++) {
            Ad[i] = p0[i];
            Ad[1280 + i] = p1[i];
            Bd[i] = pb[i];
        }
    };

    constexpr int NIT = KD / 32;
    uint4 ra0 = *(const uint4*)Ap0;
    uint4 ra1 = *(const uint4*)Ap1;
    uint4 rb  = *(const uint4*)Bp;
    store_tile(0, ra0, ra1, rb);
    __syncthreads();

    for (int it = 0; it < NIT; ++it) {
        const int cur = it & 1;
        const bool more = (it + 1 < NIT);
        if (more) {
            int ko = (it + 1) * 32;
            ra0 = *(const uint4*)(Ap0 + ko);
            ra1 = *(const uint4*)(Ap1 + ko);
            rb  = *(const uint4*)(Bp  + ko);
        }
        const uint32_t aOff = (uint32_t)cur * 10240u;
        const uint32_t bOff = (uint32_t)cur * 5120u;
#pragma unroll
        for (int kk = 0; kk < 2; kk++) {
            uint32_t a0[4], a1[4], b0[4], b1[4];
            ldsm4(a0, aAddr0 + aOff + kk * 32);
            ldsm4(a1, aAddr1 + aOff + kk * 32);
            ldsm4(b0, bAddr0 + bOff + kk * 32);
            ldsm4(b1, bAddr1 + bOff + kk * 32);
            mma_bf(acc[0][0], a0, b0[0], b0[1]);
            mma_bf(acc[0][1], a0, b0[2], b0[3]);
            mma_bf(acc[0][2], a0, b1[0], b1[1]);
            mma_bf(acc[0][3], a0, b1[2], b1[3]);
            mma_bf(acc[1][0], a1, b0[0], b0[1]);
            mma_bf(acc[1][1], a1, b0[2], b0[3]);
            mma_bf(acc[1][2], a1, b1[0], b1[1]);
            mma_bf(acc[1][3], a1, b1[2], b1[3]);
        }
        if (more) store_tile(cur ^ 1, ra0, ra1, rb);
        __syncthreads();
    }

    // ----- epilogue -----
    const int mbase = m0 + warpM * 32;
    const int nbase = n0 + warpN * 32;
#pragma unroll
    for (int mt = 0; mt < 2; mt++) {
#pragma unroll
        for (int h = 0; h < 2; h++) {
            int r = mbase + mt * 16 + gid + h * 8;
            size_t dstrow = 0;
            if (EPI == EPI_PROJ) {
                int w = r / NTOK, n = r - w * NTOK;
                int bi = w >> 6, wi = w & 63, wh = wi >> 3, ww = wi & 7;
                int ii = n / WSZ, jj = n - ii * WSZ;
                int hp = wh * WSZ + ii + SSZ; if (hp >= HIMG) hp -= HIMG;
                int wp = ww * WSZ + jj + SSZ; if (wp >= WIMG) wp -= WIMG;
                dstrow = ((size_t)bi * (HIMG * WIMG) + (size_t)hp * WIMG + wp);
            }
#pragma unroll
            for (int nt = 0; nt < 4; nt++) {
                int n = nbase + nt * 8 + tig * 2;
                float2 bsv = *(const float2*)(bias + n);
                float vx = acc[mt][nt][2 * h]     + bsv.x;
                float vy = acc[mt][nt][2 * h + 1] + bsv.y;
                if (EPI == EPI_QKV) {
                    __nv_bfloat162 p(__float2bfloat16(vx), __float2bfloat16(vy));
                    *(__nv_bfloat162*)(outb + (size_t)r * QKVC + n) = p;
                } else if (EPI == EPI_PROJ) {
                    size_t dst = dstrow * CDIM + n;
                    float2 xv = *(const float2*)(extra + dst);
                    float2 v; v.x = vx + xv.x; v.y = vy + xv.y;
                    *(float2*)(outf + dst) = v;
                } else if (EPI == EPI_FC1) {
                    __nv_bfloat162 p(__float2bfloat16(gelu_exact(vx)),
                                     __float2bfloat16(gelu_exact(vy)));
                    *(__nv_bfloat162*)(outb + (size_t)r * HID + n) = p;
                } else { // EPI_FC2
                    float2 xv = *(const float2*)(outf + (size_t)r * CDIM + n);
                    float2 v; v.x = vx + xv.x; v.y = vy + xv.y;
                    *(float2*)(outf + (size_t)r * CDIM + n) = v;
                }
            }
        }
    }
}

// ---------------- window attention: one block per (window, head) -----------
__global__ void __launch_bounds__(256) attn_kernel(const float* __restrict__ bias_table)
{
    __shared__ float qs[NTOK][HD + 1], ks[NTOK][HD + 1], vs[NTOK][HD + 1];
    __shared__ float sc[NTOK][NTOK + 1];
    __shared__ float biasS[169];
    __shared__ int   regid[NTOK];

    const int blk = blockIdx.x;
    const int w = blk / HEADS, h = blk - w * HEADS;
    const int t = threadIdx.x;

    const __nv_bfloat16* qbase = g_qkv + (size_t)w * NTOK * QKVC + h * HD;
    for (int e = t; e < NTOK * HD; e += 256) {
        int n = e >> 5, d = e & 31;
        const __nv_bfloat16* row = qbase + (size_t)n * QKVC + d;
        qs[n][d] = __bfloat162float(row[0]);
        ks[n][d] = __bfloat162float(row[CDIM]);
        vs[n][d] = __bfloat162float(row[2 * CDIM]);
    }
    for (int e = t; e < 169; e += 256) biasS[e] = bias_table[e * HEADS + h];
    if (t < NTOK) {
        int wi = w & 63, wh = wi >> 3, ww = wi & 7;
        int ii = t / WSZ, jj = t - ii * WSZ;
        int p = wh * WSZ + ii, q = ww * WSZ + jj;
        int rh = p < (HIMG - WSZ) ? 0 : (p < (HIMG - SSZ) ? 1 : 2);
        int rw = q < (WIMG - WSZ) ? 0 : (q < (WIMG - SSZ) ? 1 : 2);
        regid[t] = rh * 3 + rw;
    }
    __syncthreads();

    const float scale = 0.17677669529663688f;
    for (int e = t; e < NTOK * NTOK; e += 256) {
        int n = e / NTOK, m = e - n * NTOK;
        float a = 0.f;
#pragma unroll
        for (int d = 0; d < HD; d++) a += qs[n][d] * ks[m][d];
        int i1 = n / WSZ, j1 = n - i1 * WSZ;
        int i2 = m / WSZ, j2 = m - i2 * WSZ;
        int idx = (i1 - i2 + WSZ - 1) * (2 * WSZ - 1) + (j1 - j2 + WSZ - 1);
        float msk = (regid[n] == regid[m]) ? 0.f : -100.f;
        sc[n][m] = a * scale + biasS[idx] + msk;
    }
    __syncthreads();

    if (t < NTOK) {
        float mx = -1e30f;
        for (int m = 0; m < NTOK; m++) mx = fmaxf(mx, sc[t][m]);
        float s = 0.f;
        for (int m = 0; m < NTOK; m++) { float e = expf(sc[t][m] - mx); sc[t][m] = e; s += e; }
        float inv = 1.0f / s;
        for (int m = 0; m < NTOK; m++) sc[t][m] *= inv;
    }
    __syncthreads();

    __nv_bfloat16* obase = g_att + (size_t)w * NTOK * CDIM + h * HD;
    for (int e = t; e < NTOK * HD; e += 256) {
        int n = e >> 5, d = e & 31;
        float a = 0.f;
#pragma unroll
        for (int m = 0; m < NTOK; m++) a += sc[n][m] * vs[m][d];
        obase[(size_t)n * CDIM + d] = __float2bfloat16(a);
    }
}

// ---------------- launch ----------------------------------------------------
extern "C" void kernel_launch(void* const* d_in, const int* in_sizes, int n_in,
                              void* d_out, int out_size)
{
    const float* x      = (const float*)d_in[0];
    const float* n1g    = (const float*)d_in[1];
    const float* n1b    = (const float*)d_in[2];
    const float* qkv_w  = (const float*)d_in[3];
    const float* qkv_b  = (const float*)d_in[4];
    const float* relb   = (const float*)d_in[5];
    const float* proj_w = (const float*)d_in[6];
    const float* proj_b = (const float*)d_in[7];
    const float* n2g    = (const float*)d_in[8];
    const float* n2b    = (const float*)d_in[9];
    const float* fc1_w  = (const float*)d_in[10];
    const float* fc1_b  = (const float*)d_in[11];
    const float* fc2_w  = (const float*)d_in[12];
    const float* fc2_b  = (const float*)d_in[13];
    float* out = (float*)d_out;

    __nv_bfloat16 *pxw, *pqkv, *patt, *phid, *pwqkv, *pwproj, *pwfc1, *pwfc2;
    cudaGetSymbolAddress((void**)&pxw,   g_xw);
    cudaGetSymbolAddress((void**)&pqkv,  g_qkv);
    cudaGetSymbolAddress((void**)&patt,  g_att);
    cudaGetSymbolAddress((void**)&phid,  g_hid);
    cudaGetSymbolAddress((void**)&pwqkv, g_wqkv);
    cudaGetSymbolAddress((void**)&pwproj,g_wproj);
    cudaGetSymbolAddress((void**)&pwfc1, g_wfc1);
    cudaGetSymbolAddress((void**)&pwfc2, g_wfc2);

    const int LN_BLOCKS = (int)(ROWS / 8);       // 25088
    const int MB = (int)(ROWS / 128);            // 1568

    // 0) weight conversion (tiny)
    w2bf_kernel<<<(QKVC * CDIM + 255) / 256, 256>>>(qkv_w,  pwqkv,  QKVC * CDIM);
    w2bf_kernel<<<(CDIM * CDIM + 255) / 256, 256>>>(proj_w, pwproj, CDIM * CDIM);
    w2bf_kernel<<<(HID * CDIM + 255) / 256, 256>>>(fc1_w,  pwfc1,  HID * CDIM);
    w2bf_kernel<<<(CDIM * HID + 255) / 256, 256>>>(fc2_w,  pwfc2,  CDIM * HID);

    // 1) LN1 + shift + window partition  -> g_xw (bf16)
    ln_kernel<true><<<LN_BLOCKS, 256>>>(x, n1g, n1b);
    // 2) QKV GEMM
    gemm_bf<192, EPI_QKV><<<dim3(QKVC / 64, MB), 256>>>(pxw, pwqkv, qkv_b, nullptr, pqkv, nullptr);
    // 3) window attention
    attn_kernel<<<NWIN * HEADS, 256>>>(relb);
    // 4) proj GEMM + window-reverse + roll + residual -> d_out (f32)
    gemm_bf<192, EPI_PROJ><<<dim3(CDIM / 64, MB), 256>>>(patt, pwproj, proj_b, out, nullptr, x);
    // 5) LN2 -> g_xw (bf16)
    ln_kernel<false><<<LN_BLOCKS, 256>>>(out, n2g, n2b);
    // 6) fc1 + GELU -> g_hid (bf16)
    gemm_bf<192, EPI_FC1><<<dim3(HID / 64, MB), 256>>>(pxw, pwfc1, fc1_b, nullptr, phid, nullptr);
    // 7) fc2 + residual -> d_out (f32)
    gemm_bf<768, EPI_FC2><<<dim3(CDIM / 64, MB), 256>>>(phid, pwfc2, fc2_b, out, nullptr, nullptr);
}

// round 4
// speedup vs baseline: 4.4124x; 1.8849x over previous
#include <cuda_runtime.h>
#include <cuda_bf16.h>
#include <math.h>
#include <stdint.h>

// ---------------- problem constants ----------------
constexpr int BATCH = 64, HIMG = 56, WIMG = 56, CDIM = 192;
constexpr int HEADS = 6, HD = 32, WSZ = 7, SSZ = 3, NWG = 8, NTOK = 49;
constexpr int NWIN = BATCH * NWG * NWG;          // 4096
constexpr size_t ROWS = (size_t)NWIN * NTOK;     // 200704
constexpr int HID = 768, QKVC = 576;

// ---------------- scratch (device globals; no runtime alloc) ----------------
__device__ __nv_bfloat16 g_xw [ROWS * CDIM];
__device__ __nv_bfloat16 g_qkv[ROWS * QKVC];
__device__ __nv_bfloat16 g_att[ROWS * CDIM];
__device__ __nv_bfloat16 g_hid[ROWS * HID];
__device__ __nv_bfloat16 g_wqkv[QKVC * CDIM];
__device__ __nv_bfloat16 g_wproj[CDIM * CDIM];
__device__ __nv_bfloat16 g_wfc1[HID * CDIM];
__device__ __nv_bfloat16 g_wfc2[CDIM * HID];

// ---------------- helpers ----------------
__device__ __forceinline__ void ldsm4(uint32_t* r, uint32_t addr) {
    asm volatile("ldmatrix.sync.aligned.m8n8.x4.shared.b16 {%0,%1,%2,%3}, [%4];"
        : "=r"(r[0]), "=r"(r[1]), "=r"(r[2]), "=r"(r[3]) : "r"(addr));
}
__device__ __forceinline__ void mma_bf(float* c, const uint32_t* a, uint32_t b0, uint32_t b1) {
    asm volatile(
        "mma.sync.aligned.m16n8k16.row.col.f32.bf16.bf16.f32 "
        "{%0,%1,%2,%3}, {%4,%5,%6,%7}, {%8,%9}, {%0,%1,%2,%3};"
        : "+f"(c[0]), "+f"(c[1]), "+f"(c[2]), "+f"(c[3])
        : "r"(a[0]), "r"(a[1]), "r"(a[2]), "r"(a[3]), "r"(b0), "r"(b1));
}
__device__ __forceinline__ void cpa16(uint32_t dst, const void* src) {
    asm volatile("cp.async.ca.shared.global [%0], [%1], 16;" :: "r"(dst), "l"(src));
}
__device__ __forceinline__ void cpcommit() { asm volatile("cp.async.commit_group;"); }
template<int N> __device__ __forceinline__ void cpwait() {
    asm volatile("cp.async.wait_group %0;" :: "n"(N));
}
__device__ __forceinline__ float gelu_exact(float v) {
    return 0.5f * v * (1.0f + erff(v * 0.70710678118654752f));
}

// ---------------- weight conversion ----------------
__global__ void w2bf_kernel(const float* __restrict__ s, __nv_bfloat16* __restrict__ d, int n)
{
    int i = blockIdx.x * blockDim.x + threadIdx.x;
    if (i < n) d[i] = __float2bfloat16(s[i]);
}

// ---------------- LayerNorm (+ optional shift/window gather), bf16 out ------
template<bool WIN>
__global__ void __launch_bounds__(256) ln_kernel(const float* __restrict__ x,
                                                 const float* __restrict__ gg,
                                                 const float* __restrict__ bb)
{
    int warp = (blockIdx.x << 3) + (threadIdx.x >> 5);
    int lane = threadIdx.x & 31;
    size_t src;
    if (WIN) {
        int w = warp / NTOK, n = warp - w * NTOK;
        int bi = w >> 6, wi = w & 63, wh = wi >> 3, ww = wi & 7;
        int ii = n / WSZ, jj = n - ii * WSZ;
        int hs = wh * WSZ + ii + SSZ; if (hs >= HIMG) hs -= HIMG;
        int ws_ = ww * WSZ + jj + SSZ; if (ws_ >= WIMG) ws_ -= WIMG;
        src = ((size_t)bi * (HIMG * WIMG) + (size_t)hs * WIMG + ws_) * CDIM;
    } else {
        src = (size_t)warp * CDIM;
    }
    const float* xr = x + src;
    float v[6]; float s = 0.f;
#pragma unroll
    for (int t = 0; t < 6; t++) { v[t] = xr[lane + 32 * t]; s += v[t]; }
#pragma unroll
    for (int o = 16; o; o >>= 1) s += __shfl_xor_sync(0xffffffffu, s, o);
    float mu = s * (1.0f / CDIM);
    float vs = 0.f;
#pragma unroll
    for (int t = 0; t < 6; t++) { float d = v[t] - mu; vs += d * d; }
#pragma unroll
    for (int o = 16; o; o >>= 1) vs += __shfl_xor_sync(0xffffffffu, vs, o);
    float inv = rsqrtf(vs * (1.0f / CDIM) + 1e-5f);
    __nv_bfloat16* op = g_xw + (size_t)warp * CDIM;
#pragma unroll
    for (int t = 0; t < 6; t++) {
        int c = lane + 32 * t;
        op[c] = __float2bfloat16((v[t] - mu) * inv * gg[c] + bb[c]);
    }
}

// ---------------- bf16 tensor-core GEMM --------------------------------------
// BM=128, BN=64, BK=32; 128 threads = 4 warps (2M x 2N), warp tile 64x32.
// cp.async double-buffered.
enum { EPI_QKV = 0, EPI_PROJ = 1, EPI_FC1 = 2, EPI_FC2 = 3 };

template<int KD, int EPI>
__global__ void __launch_bounds__(128) gemm_bf(
    const __nv_bfloat16* __restrict__ A, const __nv_bfloat16* __restrict__ Wm,
    const float* __restrict__ bias, float* __restrict__ outf,
    __nv_bfloat16* __restrict__ outb, const float* __restrict__ extra)
{
    // As[2][128][20u32], Bs[2][64][20u32]; row stride 80B
    __shared__ uint32_t sm[2 * 2560 + 2 * 1280];
    const int t = threadIdx.x, lane = t & 31, w4 = t >> 5;
    const int warpM = w4 & 1, warpN = w4 >> 1;
    const int m0 = blockIdx.y * 128, n0 = blockIdx.x * 64;
    const int gid = lane >> 2, tig = lane & 3;
    const int lr = t >> 2, seg = t & 3;

    const __nv_bfloat16* Ap = A  + (size_t)(m0 + lr) * KD + seg * 8;
    const __nv_bfloat16* Bp = Wm + (size_t)(n0 + lr) * KD + seg * 8;
    const uint32_t smb = (uint32_t)__cvta_generic_to_shared(sm);
    const uint32_t aSt = smb + (uint32_t)((lr * 20 + seg * 4) * 4);
    const uint32_t bSt = smb + 20480u + (uint32_t)((lr * 20 + seg * 4) * 4);

    auto issue = [&](int buf, int k0) {
#pragma unroll
        for (int p = 0; p < 4; p++)
            cpa16(aSt + buf * 10240u + p * 2560u, Ap + (size_t)p * 32 * KD + k0);
#pragma unroll
        for (int q = 0; q < 2; q++)
            cpa16(bSt + buf * 5120u + q * 2560u, Bp + (size_t)q * 32 * KD + k0);
        cpcommit();
    };

    const uint32_t aRd = smb + (uint32_t)(((warpM * 64 + (lane & 15)) * 80) + (lane >> 4) * 16);
    const uint32_t bRd = smb + 20480u +
        (uint32_t)(((warpN * 32 + (lane & 7) + ((lane & 16) >> 1)) * 80) + ((lane >> 3) & 1) * 16);

    float acc[4][4][4];
#pragma unroll
    for (int i = 0; i < 4; i++)
#pragma unroll
        for (int j = 0; j < 4; j++)
#pragma unroll
            for (int r = 0; r < 4; r++) acc[i][j][r] = 0.f;

    constexpr int NIT = KD / 32;
    issue(0, 0);
    for (int it = 0; it < NIT; ++it) {
        const int cur = it & 1;
        cpwait<0>();
        __syncthreads();
        if (it + 1 < NIT) issue(cur ^ 1, (it + 1) * 32);
        const uint32_t aO = aRd + cur * 10240u;
        const uint32_t bO = bRd + cur * 5120u;
#pragma unroll
        for (int kk = 0; kk < 2; kk++) {
            uint32_t a[4][4], b0[4], b1[4];
#pragma unroll
            for (int mt = 0; mt < 4; mt++) ldsm4(a[mt], aO + mt * 1280u + kk * 32);
            ldsm4(b0, bO + kk * 32);
            ldsm4(b1, bO + 1280u + kk * 32);
#pragma unroll
            for (int mt = 0; mt < 4; mt++) {
                mma_bf(acc[mt][0], a[mt], b0[0], b0[1]);
                mma_bf(acc[mt][1], a[mt], b0[2], b0[3]);
                mma_bf(acc[mt][2], a[mt], b1[0], b1[1]);
                mma_bf(acc[mt][3], a[mt], b1[2], b1[3]);
            }
        }
        __syncthreads();
    }

    // ----- epilogue -----
    const int mbase = m0 + warpM * 64;
    const int nbase = n0 + warpN * 32;
#pragma unroll
    for (int mt = 0; mt < 4; mt++) {
#pragma unroll
        for (int h = 0; h < 2; h++) {
            int r = mbase + mt * 16 + gid + h * 8;
            size_t dstrow = 0;
            if (EPI == EPI_PROJ) {
                int w = r / NTOK, n = r - w * NTOK;
                int bi = w >> 6, wi = w & 63, wh = wi >> 3, ww = wi & 7;
                int ii = n / WSZ, jj = n - ii * WSZ;
                int hp = wh * WSZ + ii + SSZ; if (hp >= HIMG) hp -= HIMG;
                int wp = ww * WSZ + jj + SSZ; if (wp >= WIMG) wp -= WIMG;
                dstrow = ((size_t)bi * (HIMG * WIMG) + (size_t)hp * WIMG + wp);
            }
#pragma unroll
            for (int nt = 0; nt < 4; nt++) {
                int n = nbase + nt * 8 + tig * 2;
                float2 bsv = *(const float2*)(bias + n);
                float vx = acc[mt][nt][2 * h]     + bsv.x;
                float vy = acc[mt][nt][2 * h + 1] + bsv.y;
                if (EPI == EPI_QKV) {
                    __nv_bfloat162 p(__float2bfloat16(vx), __float2bfloat16(vy));
                    *(__nv_bfloat162*)(outb + (size_t)r * QKVC + n) = p;
                } else if (EPI == EPI_PROJ) {
                    size_t dst = dstrow * CDIM + n;
                    float2 xv = *(const float2*)(extra + dst);
                    float2 v; v.x = vx + xv.x; v.y = vy + xv.y;
                    *(float2*)(outf + dst) = v;
                } else if (EPI == EPI_FC1) {
                    __nv_bfloat162 p(__float2bfloat16(gelu_exact(vx)),
                                     __float2bfloat16(gelu_exact(vy)));
                    *(__nv_bfloat162*)(outb + (size_t)r * HID + n) = p;
                } else {
                    float2 xv = *(const float2*)(outf + (size_t)r * CDIM + n);
                    float2 v; v.x = vx + xv.x; v.y = vy + xv.y;
                    *(float2*)(outf + (size_t)r * CDIM + n) = v;
                }
            }
        }
    }
}

// ---------------- tensor-core window attention -------------------------------
// one block = one (window, head); 128 threads = 4 warps; tokens padded 49->64.
// S = Q K^T (64x64), softmax in regs, P bf16 -> smem, O = P V^T (64x32).
__global__ void __launch_bounds__(128) attn_tc(const float* __restrict__ bias_table)
{
    // u32 offsets: Qs[64][20]=1280, Ks[64][20]=1280, Vt[32][36]=1152, P[64][36]=2304
    __shared__ uint32_t sm[1280 + 1280 + 1152 + 2304];
    __shared__ float biasS[169];
    __shared__ int   regid[NTOK];
    constexpr int QS = 0, KS = 1280, VT = 2560, PS = 3712;

    const int blk = blockIdx.x;
    const int w = blk / HEADS, h = blk - w * HEADS;
    const int t = threadIdx.x, lane = t & 31, w4 = t >> 5;
    const int gid = lane >> 2, tig = lane & 3;

    char* smc = (char*)sm;
    const __nv_bfloat16* base = g_qkv + (size_t)w * NTOK * QKVC + (size_t)h * HD;

    // load Q, K (49 rows x 32 bf16 = 4 segs of 16B)
    for (int e = t; e < NTOK * 4; e += 128) {
        int n = e >> 2, s = e & 3;
        const char* rp = (const char*)(base + (size_t)n * QKVC) + s * 16;
        *(uint4*)(smc + QS * 4 + n * 80 + s * 16) = *(const uint4*)rp;
        *(uint4*)(smc + KS * 4 + n * 80 + s * 16) = *(const uint4*)(rp + CDIM * 2);
    }
    // zero-pad rows 49..63
    for (int e = t; e < 15 * 4; e += 128) {
        int n = 49 + (e >> 2), s = e & 3;
        uint4 z = {0, 0, 0, 0};
        *(uint4*)(smc + QS * 4 + n * 80 + s * 16) = z;
        *(uint4*)(smc + KS * 4 + n * 80 + s * 16) = z;
    }
    // V transposed: Vt[d][tok], row stride 144B
    for (int e = t; e < NTOK * HD; e += 128) {
        int n = e >> 5, d = e & 31;
        ((__nv_bfloat16*)(smc + VT * 4 + d * 144))[n] = base[(size_t)n * QKVC + 2 * CDIM + d];
    }
    for (int e = t; e < HD * 15; e += 128) {
        int d = e / 15, n = 49 + e % 15;
        ((__nv_bfloat16*)(smc + VT * 4 + d * 144))[n] = __nv_bfloat16(0.f);
    }
    for (int e = t; e < 169; e += 128) biasS[e] = bias_table[e * HEADS + h];
    if (t < NTOK) {
        int wi = w & 63, wh = wi >> 3, ww = wi & 7;
        int ii = t / WSZ, jj = t - ii * WSZ;
        int p = wh * WSZ + ii, q = ww * WSZ + jj;
        int rh = p < (HIMG - WSZ) ? 0 : (p < (HIMG - SSZ) ? 1 : 2);
        int rw = q < (WIMG - WSZ) ? 0 : (q < (WIMG - SSZ) ? 1 : 2);
        regid[t] = rh * 3 + rw;
    }
    __syncthreads();

    const uint32_t smb = (uint32_t)__cvta_generic_to_shared(sm);
    // ---- S = Q K^T : warp w4 owns 16-row m-strip, all 64 cols ----
    const uint32_t aQ = smb + QS * 4 + (w4 * 16 + (lane & 15)) * 80 + (lane >> 4) * 16;
    const uint32_t bK = smb + KS * 4 +
        ((lane & 7) + ((lane & 16) >> 1)) * 80 + ((lane >> 3) & 1) * 16;
    float acc[8][4];
#pragma unroll
    for (int i = 0; i < 8; i++)
#pragma unroll
        for (int j = 0; j < 4; j++) acc[i][j] = 0.f;
#pragma unroll
    for (int kk = 0; kk < 2; kk++) {
        uint32_t a[4]; ldsm4(a, aQ + kk * 32);
#pragma unroll
        for (int ntp = 0; ntp < 4; ntp++) {
            uint32_t b[4]; ldsm4(b, bK + ntp * 1280u + kk * 32);
            mma_bf(acc[2 * ntp],     a, b[0], b[1]);
            mma_bf(acc[2 * ntp + 1], a, b[2], b[3]);
        }
    }

    // ---- bias + mask + softmax (row on 4 lanes: shfl_xor 1,2) ----
    const float scale = 0.17677669529663688f;
#pragma unroll
    for (int rr = 0; rr < 2; rr++) {
        int r = w4 * 16 + gid + rr * 8;
        float vv[16];
        int i1 = 0, j1 = 0, rid = -1;
        bool rv = (r < NTOK);
        if (rv) { i1 = r / WSZ; j1 = r - i1 * WSZ; rid = regid[r]; }
        float mx = -1e30f;
#pragma unroll
        for (int i = 0; i < 16; i++) {
            int c = (i >> 1) * 8 + tig * 2 + (i & 1);
            float v = -1e30f;
            if (rv && c < NTOK) {
                int i2 = (c * 9363) >> 16;
                int j2 = c - i2 * WSZ;
                float msk = (rid == regid[c]) ? 0.f : -100.f;
                v = acc[i >> 1][(i & 1) + 2 * rr] * scale
                  + biasS[(i1 - i2 + WSZ - 1) * (2 * WSZ - 1) + (j1 - j2 + WSZ - 1)] + msk;
            }
            vv[i] = v; mx = fmaxf(mx, v);
        }
        mx = fmaxf(mx, __shfl_xor_sync(0xffffffffu, mx, 1));
        mx = fmaxf(mx, __shfl_xor_sync(0xffffffffu, mx, 2));
        float sum = 0.f;
#pragma unroll
        for (int i = 0; i < 16; i++) { vv[i] = __expf(vv[i] - mx); sum += vv[i]; }
        sum += __shfl_xor_sync(0xffffffffu, sum, 1);
        sum += __shfl_xor_sync(0xffffffffu, sum, 2);
        float inv = 1.0f / sum;
#pragma unroll
        for (int nt = 0; nt < 8; nt++) {
            int c = nt * 8 + tig * 2;
            __nv_bfloat162 p(__float2bfloat16(vv[2 * nt] * inv),
                             __float2bfloat16(vv[2 * nt + 1] * inv));
            *(__nv_bfloat162*)(smc + PS * 4 + r * 144 + c * 2) = p;
        }
    }
    __syncwarp();

    // ---- O = P V^T : 16-row strip x 32 cols, K=64 ----
    const uint32_t aP = smb + PS * 4 + (w4 * 16 + (lane & 15)) * 144 + (lane >> 4) * 16;
    const uint32_t bV = smb + VT * 4 +
        ((lane & 7) + ((lane & 16) >> 1)) * 144 + ((lane >> 3) & 1) * 16;
    float oa[4][4];
#pragma unroll
    for (int i = 0; i < 4; i++)
#pragma unroll
        for (int j = 0; j < 4; j++) oa[i][j] = 0.f;
#pragma unroll
    for (int ks = 0; ks < 4; ks++) {
        uint32_t a[4]; ldsm4(a, aP + ks * 32);
        uint32_t b0[4], b1[4];
        ldsm4(b0, bV + ks * 32);
        ldsm4(b1, bV + 16 * 144 + ks * 32);
        mma_bf(oa[0], a, b0[0], b0[1]);
        mma_bf(oa[1], a, b0[2], b0[3]);
        mma_bf(oa[2], a, b1[0], b1[1]);
        mma_bf(oa[3], a, b1[2], b1[3]);
    }
    __nv_bfloat16* ob = g_att + (size_t)w * NTOK * CDIM + (size_t)h * HD;
#pragma unroll
    for (int rr = 0; rr < 2; rr++) {
        int r = w4 * 16 + gid + rr * 8;
        if (r < NTOK) {
#pragma unroll
            for (int nt = 0; nt < 4; nt++) {
                int c = nt * 8 + tig * 2;
                __nv_bfloat162 p(__float2bfloat16(oa[nt][2 * rr]),
                                 __float2bfloat16(oa[nt][2 * rr + 1]));
                *(__nv_bfloat162*)(ob + (size_t)r * CDIM + c) = p;
            }
        }
    }
}

// ---------------- launch ----------------------------------------------------
extern "C" void kernel_launch(void* const* d_in, const int* in_sizes, int n_in,
                              void* d_out, int out_size)
{
    const float* x      = (const float*)d_in[0];
    const float* n1g    = (const float*)d_in[1];
    const float* n1b    = (const float*)d_in[2];
    const float* qkv_w  = (const float*)d_in[3];
    const float* qkv_b  = (const float*)d_in[4];
    const float* relb   = (const float*)d_in[5];
    const float* proj_w = (const float*)d_in[6];
    const float* proj_b = (const float*)d_in[7];
    const float* n2g    = (const float*)d_in[8];
    const float* n2b    = (const float*)d_in[9];
    const float* fc1_w  = (const float*)d_in[10];
    const float* fc1_b  = (const float*)d_in[11];
    const float* fc2_w  = (const float*)d_in[12];
    const float* fc2_b  = (const float*)d_in[13];
    float* out = (float*)d_out;

    __nv_bfloat16 *pxw, *pqkv, *patt, *phid, *pwqkv, *pwproj, *pwfc1, *pwfc2;
    cudaGetSymbolAddress((void**)&pxw,   g_xw);
    cudaGetSymbolAddress((void**)&pqkv,  g_qkv);
    cudaGetSymbolAddress((void**)&patt,  g_att);
    cudaGetSymbolAddress((void**)&phid,  g_hid);
    cudaGetSymbolAddress((void**)&pwqkv, g_wqkv);
    cudaGetSymbolAddress((void**)&pwproj,g_wproj);
    cudaGetSymbolAddress((void**)&pwfc1, g_wfc1);
    cudaGetSymbolAddress((void**)&pwfc2, g_wfc2);

    const int LN_BLOCKS = (int)(ROWS / 8);       // 25088
    const int MB = (int)(ROWS / 128);            // 1568

    w2bf_kernel<<<(QKVC * CDIM + 255) / 256, 256>>>(qkv_w,  pwqkv,  QKVC * CDIM);
    w2bf_kernel<<<(CDIM * CDIM + 255) / 256, 256>>>(proj_w, pwproj, CDIM * CDIM);
    w2bf_kernel<<<(HID * CDIM + 255) / 256, 256>>>(fc1_w,  pwfc1,  HID * CDIM);
    w2bf_kernel<<<(CDIM * HID + 255) / 256, 256>>>(fc2_w,  pwfc2,  CDIM * HID);

    ln_kernel<true><<<LN_BLOCKS, 256>>>(x, n1g, n1b);
    gemm_bf<192, EPI_QKV><<<dim3(QKVC / 64, MB), 128>>>(pxw, pwqkv, qkv_b, nullptr, pqkv, nullptr);
    attn_tc<<<NWIN * HEADS, 128>>>(relb);
    gemm_bf<192, EPI_PROJ><<<dim3(CDIM / 64, MB), 128>>>(patt, pwproj, proj_b, out, nullptr, x);
    ln_kernel<false><<<LN_BLOCKS, 256>>>(out, n2g, n2b);
    gemm_bf<192, EPI_FC1><<<dim3(HID / 64, MB), 128>>>(pxw, pwfc1, fc1_b, nullptr, phid, nullptr);
    gemm_bf<768, EPI_FC2><<<dim3(CDIM / 64, MB), 128>>>(phid, pwfc2, fc2_b, out, nullptr, nullptr);
}